// round 3
// baseline (speedup 1.0000x reference)
#include <cuda_runtime.h>
#include <cuda_bf16.h>

// YOLO loss, fused single pass + hierarchical reduction.
// pred/target: (N, S, S, 5*B + C) = (16384, 7, 7, 30) fp32. Output: scalar fp32.

#define S 7
#define CH 30
#define TOTAL_CELLS (16384 * S * S)
#define STEP (1.0f / 7.0f)
#define LAMBDA_COORD 5.0f
#define LAMBDA_NOOBJ 0.5f
#define EPS 1e-10f
#define INV_N (1.0f / 16384.0f)

__device__ __forceinline__ float warp_reduce(float v) {
#pragma unroll
    for (int off = 16; off > 0; off >>= 1)
        v += __shfl_xor_sync(0xFFFFFFFFu, v, off);
    return v;
}

__global__ __launch_bounds__(256, 8)
void yolo_loss_kernel(const float* __restrict__ pred,
                      const float* __restrict__ target,
                      float* __restrict__ out) {
    const int cell = blockIdx.x * blockDim.x + threadIdx.x;

    float loss = 0.0f;
    if (cell < TOTAL_CELLS) {
        // Load 30 pred + 30 target floats via float2 (base = cell*120B, 8B aligned).
        float pv[CH], tv[CH];
        const float2* p2 = reinterpret_cast<const float2*>(pred + (size_t)cell * CH);
        const float2* t2 = reinterpret_cast<const float2*>(target + (size_t)cell * CH);
#pragma unroll
        for (int i = 0; i < CH / 2; i++) {
            float2 a = p2[i];
            pv[2 * i] = a.x; pv[2 * i + 1] = a.y;
        }
#pragma unroll
        for (int i = 0; i < CH / 2; i++) {
            float2 a = t2[i];
            tv[2 * i] = a.x; tv[2 * i + 1] = a.y;
        }

        const int rem = cell % (S * S);
        const float gy = (float)(rem / S);   // axis 1 index
        const float gx = (float)(rem % S);   // axis 2 index

        const float cell_mask = (tv[9] > 0.0f) ? 1.0f : 0.0f;

        // Per-box IoU between converted pred box b and converted target box b.
        float iou[2];
#pragma unroll
        for (int b = 0; b < 2; b++) {
            const int o = 5 * b;
            // convert pred box (clip all outputs at 0)
            float pw = fmaxf(pv[o + 2], 0.0f);
            float ph = fmaxf(pv[o + 3], 0.0f);
            float px = fmaxf((pv[o + 0] + gx) * STEP - pv[o + 2] * 0.5f, 0.0f);
            float py = fmaxf((pv[o + 1] + gy) * STEP - pv[o + 3] * 0.5f, 0.0f);
            // convert target box
            float tw = fmaxf(tv[o + 2], 0.0f);
            float th = fmaxf(tv[o + 3], 0.0f);
            float tx = fmaxf((tv[o + 0] + gx) * STEP - tv[o + 2] * 0.5f, 0.0f);
            float ty = fmaxf((tv[o + 1] + gy) * STEP - tv[o + 3] * 0.5f, 0.0f);

            float inter_w = fmaxf(pw + tw - (fmaxf(px + pw, tx + tw) - fminf(px, tx)), 0.0f);
            float inter_h = fmaxf(ph + th - (fmaxf(py + ph, ty + th) - fminf(py, ty)), 0.0f);
            float inter = inter_w * inter_h;
            float uni = pw * ph + tw * th - inter;
            iou[b] = inter / (uni + EPS);
        }

        // argmax (ties -> box 0, matching jnp.argmax first-occurrence)
        const int resp = (iou[1] > iou[0]) ? 1 : 0;

#pragma unroll
        for (int b = 0; b < 2; b++) {
            const int o = 5 * b;
            const float ob = (b == resp) ? cell_mask : 0.0f;
            // coord loss
            float c = 0.0f;
#pragma unroll
            for (int k = 0; k < 4; k++) {
                float d = pv[o + k] - tv[o + k];
                c += d * d;
            }
            loss += LAMBDA_COORD * ob * c;
            // conf loss (target = stop_gradient(iou))
            float dc = pv[o + 4] - iou[b];
            loss += ob * dc * dc;
            // noobj loss
            loss += LAMBDA_NOOBJ * (1.0f - ob) * pv[o + 4] * pv[o + 4];
        }

        // class loss
        float cl = 0.0f;
#pragma unroll
        for (int c = 10; c < CH; c++) {
            float d = pv[c] - tv[c];
            cl += d * d;
        }
        loss += cell_mask * cl;
    }

    // block reduction
    __shared__ float warp_sums[8];
    loss = warp_reduce(loss);
    const int lane = threadIdx.x & 31;
    const int wid = threadIdx.x >> 5;
    if (lane == 0) warp_sums[wid] = loss;
    __syncthreads();
    if (wid == 0) {
        float v = (lane < (blockDim.x >> 5)) ? warp_sums[lane] : 0.0f;
        v = warp_reduce(v);
        if (lane == 0) atomicAdd(out, v * INV_N);
    }
}

extern "C" void kernel_launch(void* const* d_in, const int* in_sizes, int n_in,
                              void* d_out, int out_size) {
    const float* pred = (const float*)d_in[0];
    const float* target = (const float*)d_in[1];
    float* out = (float*)d_out;

    cudaMemsetAsync(out, 0, (size_t)out_size * sizeof(float));

    const int threads = 256;
    const int blocks = (TOTAL_CELLS + threads - 1) / threads;  // 3136
    yolo_loss_kernel<<<blocks, threads>>>(pred, target, out);
}

// round 5
// speedup vs baseline: 2.0061x; 2.0061x over previous
#include <cuda_runtime.h>
#include <cuda_bf16.h>

// YOLO loss, fused single pass + smem-staged coalesced loads + hierarchical reduction.
// pred/target: (16384, 7, 7, 30) fp32. Output: scalar fp32.

#define S 7
#define CH 30
#define TOTAL_CELLS (16384 * S * S)
#define STEP (1.0f / 7.0f)
#define LAMBDA_COORD 5.0f
#define LAMBDA_NOOBJ 0.5f
#define EPS 1e-10f
#define INV_N (1.0f / 16384.0f)

#define TPB 128
#define CELLS_PER_BLOCK TPB                 // 128 cells
#define FLOATS_PER_BLOCK (CELLS_PER_BLOCK * CH)   // 3840 floats
#define VEC4_PER_BLOCK (FLOATS_PER_BLOCK / 4)     // 960 float4

__device__ __forceinline__ float warp_reduce(float v) {
#pragma unroll
    for (int off = 16; off > 0; off >>= 1)
        v += __shfl_xor_sync(0xFFFFFFFFu, v, off);
    return v;
}

__global__ __launch_bounds__(TPB)
void yolo_loss_kernel(const float* __restrict__ pred,
                      const float* __restrict__ target,
                      float* __restrict__ out) {
    __shared__ float sp[FLOATS_PER_BLOCK];
    __shared__ float st[FLOATS_PER_BLOCK];

    const size_t base = (size_t)blockIdx.x * FLOATS_PER_BLOCK;
    const float4* __restrict__ pg = reinterpret_cast<const float4*>(pred + base);
    const float4* __restrict__ tg = reinterpret_cast<const float4*>(target + base);
    float4* sp4 = reinterpret_cast<float4*>(sp);
    float4* st4 = reinterpret_cast<float4*>(st);

    // Coalesced staging: 960 float4 per array, 128 threads -> 7 full rounds + 64-thread tail.
    {
        float4 rp[8], rt[8];
#pragma unroll
        for (int i = 0; i < 7; i++) {
            rp[i] = pg[threadIdx.x + TPB * i];
            rt[i] = tg[threadIdx.x + TPB * i];
        }
        const bool tail = threadIdx.x < (VEC4_PER_BLOCK - 7 * TPB);  // < 64
        if (tail) {
            rp[7] = pg[7 * TPB + threadIdx.x];
            rt[7] = tg[7 * TPB + threadIdx.x];
        }
#pragma unroll
        for (int i = 0; i < 7; i++) {
            sp4[threadIdx.x + TPB * i] = rp[i];
            st4[threadIdx.x + TPB * i] = rt[i];
        }
        if (tail) {
            sp4[7 * TPB + threadIdx.x] = rp[7];
            st4[7 * TPB + threadIdx.x] = rt[7];
        }
    }
    __syncthreads();

    // Per-thread compute from smem. Each cell = 15 float2; stride 15 is odd ->
    // conflict-free LDS.64 across both 16-lane phases.
    float pv[CH], tv[CH];
    {
        const float2* sp2 = reinterpret_cast<const float2*>(sp) + threadIdx.x * (CH / 2);
        const float2* st2 = reinterpret_cast<const float2*>(st) + threadIdx.x * (CH / 2);
#pragma unroll
        for (int i = 0; i < CH / 2; i++) {
            float2 a = sp2[i];
            pv[2 * i] = a.x; pv[2 * i + 1] = a.y;
        }
#pragma unroll
        for (int i = 0; i < CH / 2; i++) {
            float2 a = st2[i];
            tv[2 * i] = a.x; tv[2 * i + 1] = a.y;
        }
    }

    const int cell = blockIdx.x * TPB + threadIdx.x;
    const int rem = cell % (S * S);
    const float gy = (float)(rem / S);   // axis 1 index
    const float gx = (float)(rem % S);   // axis 2 index

    const float cell_mask = (tv[9] > 0.0f) ? 1.0f : 0.0f;

    // Per-box IoU between converted pred box b and converted target box b.
    float iou[2];
#pragma unroll
    for (int b = 0; b < 2; b++) {
        const int o = 5 * b;
        float pw = fmaxf(pv[o + 2], 0.0f);
        float ph = fmaxf(pv[o + 3], 0.0f);
        float px = fmaxf((pv[o + 0] + gx) * STEP - pv[o + 2] * 0.5f, 0.0f);
        float py = fmaxf((pv[o + 1] + gy) * STEP - pv[o + 3] * 0.5f, 0.0f);
        float tw = fmaxf(tv[o + 2], 0.0f);
        float th = fmaxf(tv[o + 3], 0.0f);
        float tx = fmaxf((tv[o + 0] + gx) * STEP - tv[o + 2] * 0.5f, 0.0f);
        float ty = fmaxf((tv[o + 1] + gy) * STEP - tv[o + 3] * 0.5f, 0.0f);

        float inter_w = fmaxf(pw + tw - (fmaxf(px + pw, tx + tw) - fminf(px, tx)), 0.0f);
        float inter_h = fmaxf(ph + th - (fmaxf(py + ph, ty + th) - fminf(py, ty)), 0.0f);
        float inter = inter_w * inter_h;
        float uni = pw * ph + tw * th - inter;
        iou[b] = inter / (uni + EPS);
    }

    // argmax (ties -> box 0, matching jnp.argmax first-occurrence)
    const int resp = (iou[1] > iou[0]) ? 1 : 0;

    float loss = 0.0f;
#pragma unroll
    for (int b = 0; b < 2; b++) {
        const int o = 5 * b;
        const float ob = (b == resp) ? cell_mask : 0.0f;
        float c = 0.0f;
#pragma unroll
        for (int k = 0; k < 4; k++) {
            float d = pv[o + k] - tv[o + k];
            c += d * d;
        }
        loss += LAMBDA_COORD * ob * c;
        float dc = pv[o + 4] - iou[b];
        loss += ob * dc * dc;
        loss += LAMBDA_NOOBJ * (1.0f - ob) * pv[o + 4] * pv[o + 4];
    }

    float cl = 0.0f;
#pragma unroll
    for (int c = 10; c < CH; c++) {
        float d = pv[c] - tv[c];
        cl += d * d;
    }
    loss += cell_mask * cl;

    // Block reduction (4 warps).
    __shared__ float warp_sums[TPB / 32];
    loss = warp_reduce(loss);
    const int lane = threadIdx.x & 31;
    const int wid = threadIdx.x >> 5;
    if (lane == 0) warp_sums[wid] = loss;
    __syncthreads();
    if (wid == 0) {
        float v = (lane < (TPB / 32)) ? warp_sums[lane] : 0.0f;
        v = warp_reduce(v);
        if (lane == 0) atomicAdd(out, v * INV_N);
    }
}

extern "C" void kernel_launch(void* const* d_in, const int* in_sizes, int n_in,
                              void* d_out, int out_size) {
    const float* pred = (const float*)d_in[0];
    const float* target = (const float*)d_in[1];
    float* out = (float*)d_out;

    cudaMemsetAsync(out, 0, (size_t)out_size * sizeof(float));

    const int blocks = TOTAL_CELLS / TPB;  // 6272, exact
    yolo_loss_kernel<<<blocks, TPB>>>(pred, target, out);
}